// round 8
// baseline (speedup 1.0000x reference)
#include <cuda_runtime.h>
#include <cstdint>
#include <cstddef>

#define HID 512
#define SEQ 2048
#define BATCH 64
#define VOCAB 32000

// ---------------- scratch ----------------
__device__ float g_E[(size_t)VOCAB * HID];          // E' = embed @ W_ih0^T + biases
__device__ float g_ys[(size_t)SEQ * BATCH * HID];   // layer-0 outputs
__device__ float g_xb[(size_t)SEQ * BATCH * HID];   // layer-1 input term

// ---------------- helpers ----------------
__device__ __forceinline__ unsigned smem_u32(const void* p) {
    unsigned r;
    asm("{ .reg .u64 t; cvta.to.shared.u64 t, %1; cvt.u32.u64 %0, t; }" : "=r"(r) : "l"(p));
    return r;
}
__device__ __forceinline__ unsigned ctarank() {
    unsigned r; asm("mov.u32 %0, %%cluster_ctarank;" : "=r"(r)); return r;
}
__device__ __forceinline__ void fma2(unsigned long long& d, unsigned long long a, unsigned long long b) {
    asm("fma.rn.f32x2 %0, %1, %2, %0;" : "+l"(d) : "l"(a), "l"(b));
}
__device__ __forceinline__ unsigned long long pack2(float a) {
    unsigned long long r; asm("mov.b64 %0, {%1, %1};" : "=l"(r) : "f"(a)); return r;
}
__device__ __forceinline__ float sum2(unsigned long long a) {
    return __uint_as_float((unsigned)a) + __uint_as_float((unsigned)(a >> 32));
}
__device__ __forceinline__ float2 unpack2(unsigned long long a) {
    return make_float2(__uint_as_float((unsigned)a), __uint_as_float((unsigned)(a >> 32)));
}

// ---------------- GEMM: C[M][512] = A[M][512] @ W[512][512]^T + bi + bh ------
#define BM 128
#define BN 128
#define BK 16

__global__ void __launch_bounds__(256)
gemm_bias_kernel(const float* __restrict__ A, const float* __restrict__ W,
                 const float* __restrict__ bi, const float* __restrict__ bh,
                 float* __restrict__ C)
{
    __shared__ float As[BK][BM + 4];
    __shared__ float Bs[BK][BN + 4];

    int bm = blockIdx.x, bn = blockIdx.y;
    int tid = threadIdx.x;
    int tx = tid & 15, ty = tid >> 4;
    int ar = tid >> 2;
    int ac = (tid & 3) << 2;

    const float* Ap = A + (size_t)bm * BM * HID;
    const float* Wp = W + (size_t)bn * BN * HID;

    unsigned long long acc[8][4];
#pragma unroll
    for (int r = 0; r < 8; ++r)
#pragma unroll
        for (int c = 0; c < 4; ++c) acc[r][c] = 0ULL;

    for (int k0 = 0; k0 < HID; k0 += BK) {
        float4 a0 = *(const float4*)&Ap[(size_t)ar * HID + k0 + ac];
        float4 a1 = *(const float4*)&Ap[(size_t)(ar + 64) * HID + k0 + ac];
        float4 b0 = *(const float4*)&Wp[(size_t)ar * HID + k0 + ac];
        float4 b1 = *(const float4*)&Wp[(size_t)(ar + 64) * HID + k0 + ac];
        __syncthreads();
        As[ac + 0][ar] = a0.x; As[ac + 1][ar] = a0.y; As[ac + 2][ar] = a0.z; As[ac + 3][ar] = a0.w;
        As[ac + 0][ar + 64] = a1.x; As[ac + 1][ar + 64] = a1.y; As[ac + 2][ar + 64] = a1.z; As[ac + 3][ar + 64] = a1.w;
        Bs[ac + 0][ar] = b0.x; Bs[ac + 1][ar] = b0.y; Bs[ac + 2][ar] = b0.z; Bs[ac + 3][ar] = b0.w;
        Bs[ac + 0][ar + 64] = b1.x; Bs[ac + 1][ar + 64] = b1.y; Bs[ac + 2][ar + 64] = b1.z; Bs[ac + 3][ar + 64] = b1.w;
        __syncthreads();
#pragma unroll
        for (int k = 0; k < BK; ++k) {
            float4 av0 = *(const float4*)&As[k][ty * 4];
            float4 av1 = *(const float4*)&As[k][ty * 4 + 64];
            ulonglong2 bv0 = *(const ulonglong2*)&Bs[k][tx * 4];
            ulonglong2 bv1 = *(const ulonglong2*)&Bs[k][tx * 4 + 64];
            unsigned long long am[8];
            am[0] = pack2(av0.x); am[1] = pack2(av0.y); am[2] = pack2(av0.z); am[3] = pack2(av0.w);
            am[4] = pack2(av1.x); am[5] = pack2(av1.y); am[6] = pack2(av1.z); am[7] = pack2(av1.w);
#pragma unroll
            for (int r = 0; r < 8; ++r) {
                fma2(acc[r][0], am[r], bv0.x);
                fma2(acc[r][1], am[r], bv0.y);
                fma2(acc[r][2], am[r], bv1.x);
                fma2(acc[r][3], am[r], bv1.y);
            }
        }
    }

    int nb = bn * BN;
    float4 x0 = *(const float4*)&bi[nb + tx * 4];
    float4 y0 = *(const float4*)&bh[nb + tx * 4];
    float4 x1 = *(const float4*)&bi[nb + tx * 4 + 64];
    float4 y1 = *(const float4*)&bh[nb + tx * 4 + 64];
    float4 bias0 = make_float4(x0.x + y0.x, x0.y + y0.y, x0.z + y0.z, x0.w + y0.w);
    float4 bias1 = make_float4(x1.x + y1.x, x1.y + y1.y, x1.z + y1.z, x1.w + y1.w);
#pragma unroll
    for (int r = 0; r < 8; ++r) {
        int row_local = (r < 4) ? (ty * 4 + r) : (64 + ty * 4 + (r - 4));
        size_t row = (size_t)(bm * BM + row_local);
        float2 p0 = unpack2(acc[r][0]), p1 = unpack2(acc[r][1]);
        float2 p2 = unpack2(acc[r][2]), p3 = unpack2(acc[r][3]);
        float4 o0 = make_float4(p0.x + bias0.x, p0.y + bias0.y, p1.x + bias0.z, p1.y + bias0.w);
        float4 o1 = make_float4(p2.x + bias1.x, p2.y + bias1.y, p3.x + bias1.z, p3.y + bias1.w);
        *(float4*)&C[row * HID + nb + tx * 4] = o0;
        *(float4*)&C[row * HID + nb + tx * 4 + 64] = o1;
    }
}

// ---------------- recurrence ----------------
// 16 clusters x 8 CTAs. Cluster owns 4 batches; CTA r owns features
// [64r, 64r+64). Thread (j=tid>>2, ks=tid&3) keeps W_hh[jbase+j][128ks..+128)
// in registers, accumulates 4 batch partials with f32x2 FMA from a
// bank-padded broadcast h buffer, butterfly-reduces over the 4-lane quad,
// applies tanh for batch b=ks, and pushes the value to all 8 CTAs via
// precomputed mapa addresses. One split cluster barrier per step.
//
// sH layout: [2 buffers][16 segs][132 floats], seg = b*4 + (k>>7), off = k&127.
// 528B segment stride => the 4 k-segments of one LDS.128 hit distinct 16B
// bank slots (conflict-free 4x16B broadcast).
#define SEGF 132
#define HBUF (16 * SEGF)          // floats per buffer = 2112
#define HBUF_BYTES (HBUF * 4)     // 8448

__global__ void __cluster_dims__(8, 1, 1) __launch_bounds__(256, 1)
rnn_layer_kernel(const float* __restrict__ xterm,  // E' (layer0) or xb1 (layer1)
                 const int* __restrict__ src,      // tokens (layer0) or nullptr
                 const float* __restrict__ Whh,    // [512][512]
                 float* __restrict__ ys,           // [S][B][512] or nullptr
                 float* __restrict__ outh)         // [64][512] final hidden
{
    __shared__ __align__(16) float sH[2 * HBUF];

    const unsigned rank = ctarank();
    const int cid = blockIdx.x >> 3;
    const int gb0 = cid << 2;                 // first batch of this cluster
    const int jbase = (int)rank << 6;
    const int tid = threadIdx.x;
    const int jq = tid >> 2;                  // 0..63 feature within slice
    const int ks = tid & 3;                   // k segment / batch lane
    const int jfull = jbase + jq;

    // W slice into registers: 128 floats = 32 x ulonglong2
    ulonglong2 w2[32];
    {
        const ulonglong2* wp =
            (const ulonglong2*)&Whh[(size_t)jfull * HID + ks * 128];
#pragma unroll
        for (int i = 0; i < 32; ++i) w2[i] = wp[i];
    }

    // zero both h buffers
    for (int i = tid; i < 2 * HBUF; i += 256) sH[i] = 0.0f;

    // writer target: k-index for readers is jfull
    const int widx = (ks * 4 + ((int)rank >> 1)) * SEGF + (((int)rank & 1) << 6) + jq;
    unsigned raddr[8];
    {
        unsigned lbase = smem_u32(&sH[widx]);
#pragma unroll
        for (int r = 0; r < 8; ++r)
            asm("mapa.shared::cluster.u32 %0, %1, %2;"
                : "=r"(raddr[r]) : "r"(lbase), "r"(r));
    }

    // x-term prefetch pipeline
    const int brow = gb0 + ks;
    float xv;
    int tok_n = 0;
    if (src) {
        int tok0 = src[(size_t)brow * SEQ + 0];
        xv = __ldg(&xterm[(size_t)tok0 * HID + jfull]);
        tok_n = src[(size_t)brow * SEQ + 1];
    } else {
        xv = __ldg(&xterm[((size_t)0 * BATCH + brow) * HID + jfull]);
    }

    __syncthreads();
    asm volatile("barrier.cluster.arrive.aligned;" ::: "memory");
    asm volatile("barrier.cluster.wait.aligned;" ::: "memory");

    for (int t = 0; t < SEQ; ++t) {
        const float* h0p = sH + (t & 1) * HBUF + ks * SEGF;

        unsigned long long a0 = 0, a1 = 0, a2 = 0, a3 = 0;
#pragma unroll
        for (int i = 0; i < 32; ++i) {
            ulonglong2 wq = w2[i];
            ulonglong2 q0 = *(const ulonglong2*)(h0p + i * 4);
            ulonglong2 q1 = *(const ulonglong2*)(h0p + 4 * SEGF + i * 4);
            ulonglong2 q2 = *(const ulonglong2*)(h0p + 8 * SEGF + i * 4);
            ulonglong2 q3 = *(const ulonglong2*)(h0p + 12 * SEGF + i * 4);
            fma2(a0, wq.x, q0.x); fma2(a0, wq.y, q0.y);
            fma2(a1, wq.x, q1.x); fma2(a1, wq.y, q1.y);
            fma2(a2, wq.x, q2.x); fma2(a2, wq.y, q2.y);
            fma2(a3, wq.x, q3.x); fma2(a3, wq.y, q3.y);
        }

        float s0 = sum2(a0), s1 = sum2(a1), s2 = sum2(a2), s3 = sum2(a3);
        s0 += __shfl_xor_sync(0xffffffffu, s0, 1);
        s0 += __shfl_xor_sync(0xffffffffu, s0, 2);
        s1 += __shfl_xor_sync(0xffffffffu, s1, 1);
        s1 += __shfl_xor_sync(0xffffffffu, s1, 2);
        s2 += __shfl_xor_sync(0xffffffffu, s2, 1);
        s2 += __shfl_xor_sync(0xffffffffu, s2, 2);
        s3 += __shfl_xor_sync(0xffffffffu, s3, 1);
        s3 += __shfl_xor_sync(0xffffffffu, s3, 2);
        float sv = (ks == 0) ? s0 : (ks == 1) ? s1 : (ks == 2) ? s2 : s3;

        float h = tanhf(sv + xv);

        // push to all 8 CTAs' next buffer
        const unsigned hoff = ((unsigned)(t & 1) ^ 1u) * HBUF_BYTES;
#pragma unroll
        for (int r = 0; r < 8; ++r)
            asm volatile("st.shared::cluster.f32 [%0], %1;"
                         :: "r"(raddr[r] + hoff), "f"(h) : "memory");

        asm volatile("barrier.cluster.arrive.aligned;" ::: "memory");

        // overlap with barrier wait: prefetch x(t+1), drain global stores
        if (src) {
            xv = __ldg(&xterm[(size_t)tok_n * HID + jfull]);
            int tnx = (t + 2 < SEQ) ? (t + 2) : (SEQ - 1);
            tok_n = src[(size_t)brow * SEQ + tnx];
        } else {
            int tnx = (t + 1 < SEQ) ? (t + 1) : (SEQ - 1);
            xv = __ldg(&xterm[((size_t)tnx * BATCH + brow) * HID + jfull]);
        }
        if (ys) ys[((size_t)t * BATCH + brow) * HID + jfull] = h;
        if (t == SEQ - 1) outh[(size_t)brow * HID + jfull] = h;

        asm volatile("barrier.cluster.wait.aligned;" ::: "memory");
    }
}

// ---------------- launch ----------------
extern "C" void kernel_launch(void* const* d_in, const int* in_sizes, int n_in,
                              void* d_out, int out_size)
{
    const int* src = (const int*)d_in[0];
    const float* embed = (const float*)d_in[1];
    const float* W_ih = (const float*)d_in[2];   // [2][512][512]
    const float* W_hh = (const float*)d_in[3];   // [2][512][512]
    const float* b_ih = (const float*)d_in[4];   // [2][512]
    const float* b_hh = (const float*)d_in[5];   // [2][512]
    float* out = (float*)d_out;                  // [2][64][512]

    float *pE, *pYs, *pXb;
    cudaGetSymbolAddress((void**)&pE, g_E);
    cudaGetSymbolAddress((void**)&pYs, g_ys);
    cudaGetSymbolAddress((void**)&pXb, g_xb);

    // 1) E' = embed @ W_ih0^T + b_ih0 + b_hh0
    gemm_bias_kernel<<<dim3(VOCAB / BM, HID / BN), 256>>>(embed, W_ih, b_ih, b_hh, pE);
    // 2) layer-0 recurrence (gathers E'[src]), writes ys + final h
    rnn_layer_kernel<<<128, 256>>>(pE, src, W_hh, pYs, out);
    // 3) xb1 = ys @ W_ih1^T + b_ih1 + b_hh1
    gemm_bias_kernel<<<dim3(SEQ * BATCH / BM, HID / BN), 256>>>(
        pYs, W_ih + (size_t)HID * HID, b_ih + HID, b_hh + HID, pXb);
    // 4) layer-1 recurrence, writes final h
    rnn_layer_kernel<<<128, 256>>>(
        pXb, nullptr, W_hh + (size_t)HID * HID, nullptr, out + (size_t)BATCH * HID);
}

// round 10
// speedup vs baseline: 1.2476x; 1.2476x over previous
#include <cuda_runtime.h>
#include <cstdint>
#include <cstddef>

#define HID 512
#define SEQ 2048
#define BATCH 64
#define VOCAB 32000

// ---------------- scratch ----------------
__device__ float g_E[(size_t)VOCAB * HID];          // E' = embed @ W_ih0^T + biases
__device__ float g_ys[(size_t)SEQ * BATCH * HID];   // layer-0 outputs
__device__ float g_xb[(size_t)SEQ * BATCH * HID];   // layer-1 input term

// ---------------- helpers ----------------
__device__ __forceinline__ unsigned smem_u32(const void* p) {
    unsigned r;
    asm("{ .reg .u64 t; cvta.to.shared.u64 t, %1; cvt.u32.u64 %0, t; }" : "=r"(r) : "l"(p));
    return r;
}
__device__ __forceinline__ unsigned ctarank() {
    unsigned r; asm("mov.u32 %0, %%cluster_ctarank;" : "=r"(r)); return r;
}
__device__ __forceinline__ void fma2(unsigned long long& d, unsigned long long a, unsigned long long b) {
    asm("fma.rn.f32x2 %0, %1, %2, %0;" : "+l"(d) : "l"(a), "l"(b));
}
__device__ __forceinline__ unsigned long long add2(unsigned long long a, unsigned long long b) {
    unsigned long long r;
    asm("add.rn.f32x2 %0, %1, %2;" : "=l"(r) : "l"(a), "l"(b));
    return r;
}
__device__ __forceinline__ unsigned long long pack2(float a) {
    unsigned long long r; asm("mov.b64 %0, {%1, %1};" : "=l"(r) : "f"(a)); return r;
}
__device__ __forceinline__ float lo2(unsigned long long a) { return __uint_as_float((unsigned)a); }
__device__ __forceinline__ float hi2(unsigned long long a) { return __uint_as_float((unsigned)(a >> 32)); }
__device__ __forceinline__ float sum2(unsigned long long a) { return lo2(a) + hi2(a); }
__device__ __forceinline__ float2 unpack2(unsigned long long a) {
    return make_float2(lo2(a), hi2(a));
}
// acquire-cluster parity wait on local shared mbarrier
__device__ __forceinline__ void mbar_wait(unsigned mbar, unsigned parity) {
    unsigned done;
    asm volatile(
        "{\n\t.reg .pred p;\n\t"
        "mbarrier.try_wait.parity.acquire.cluster.shared::cta.b64 p, [%1], %2;\n\t"
        "selp.b32 %0, 1, 0, p;\n\t}"
        : "=r"(done) : "r"(mbar), "r"(parity) : "memory");
    if (!done) {
        asm volatile(
            "{\n\t.reg .pred P1;\n\t"
            "WL_%=:\n\t"
            "mbarrier.try_wait.parity.acquire.cluster.shared::cta.b64 P1, [%0], %1, 0x989680;\n\t"
            "@P1 bra.uni WD_%=;\n\t"
            "bra.uni WL_%=;\n\t"
            "WD_%=:\n\t}"
            :: "r"(mbar), "r"(parity) : "memory");
    }
}

// ---------------- GEMM: C[M][512] = A[M][512] @ W[512][512]^T + bi + bh ------
#define BM 128
#define BN 128
#define BK 16

__global__ void __launch_bounds__(256)
gemm_bias_kernel(const float* __restrict__ A, const float* __restrict__ W,
                 const float* __restrict__ bi, const float* __restrict__ bh,
                 float* __restrict__ C)
{
    __shared__ float As[BK][BM + 4];
    __shared__ float Bs[BK][BN + 4];

    int bm = blockIdx.x, bn = blockIdx.y;
    int tid = threadIdx.x;
    int tx = tid & 15, ty = tid >> 4;
    int ar = tid >> 2;
    int ac = (tid & 3) << 2;

    const float* Ap = A + (size_t)bm * BM * HID;
    const float* Wp = W + (size_t)bn * BN * HID;

    unsigned long long acc[8][4];
#pragma unroll
    for (int r = 0; r < 8; ++r)
#pragma unroll
        for (int c = 0; c < 4; ++c) acc[r][c] = 0ULL;

    for (int k0 = 0; k0 < HID; k0 += BK) {
        float4 a0 = *(const float4*)&Ap[(size_t)ar * HID + k0 + ac];
        float4 a1 = *(const float4*)&Ap[(size_t)(ar + 64) * HID + k0 + ac];
        float4 b0 = *(const float4*)&Wp[(size_t)ar * HID + k0 + ac];
        float4 b1 = *(const float4*)&Wp[(size_t)(ar + 64) * HID + k0 + ac];
        __syncthreads();
        As[ac + 0][ar] = a0.x; As[ac + 1][ar] = a0.y; As[ac + 2][ar] = a0.z; As[ac + 3][ar] = a0.w;
        As[ac + 0][ar + 64] = a1.x; As[ac + 1][ar + 64] = a1.y; As[ac + 2][ar + 64] = a1.z; As[ac + 3][ar + 64] = a1.w;
        Bs[ac + 0][ar] = b0.x; Bs[ac + 1][ar] = b0.y; Bs[ac + 2][ar] = b0.z; Bs[ac + 3][ar] = b0.w;
        Bs[ac + 0][ar + 64] = b1.x; Bs[ac + 1][ar + 64] = b1.y; Bs[ac + 2][ar + 64] = b1.z; Bs[ac + 3][ar + 64] = b1.w;
        __syncthreads();
#pragma unroll
        for (int k = 0; k < BK; ++k) {
            float4 av0 = *(const float4*)&As[k][ty * 4];
            float4 av1 = *(const float4*)&As[k][ty * 4 + 64];
            ulonglong2 bv0 = *(const ulonglong2*)&Bs[k][tx * 4];
            ulonglong2 bv1 = *(const ulonglong2*)&Bs[k][tx * 4 + 64];
            unsigned long long am[8];
            am[0] = pack2(av0.x); am[1] = pack2(av0.y); am[2] = pack2(av0.z); am[3] = pack2(av0.w);
            am[4] = pack2(av1.x); am[5] = pack2(av1.y); am[6] = pack2(av1.z); am[7] = pack2(av1.w);
#pragma unroll
            for (int r = 0; r < 8; ++r) {
                fma2(acc[r][0], am[r], bv0.x);
                fma2(acc[r][1], am[r], bv0.y);
                fma2(acc[r][2], am[r], bv1.x);
                fma2(acc[r][3], am[r], bv1.y);
            }
        }
    }

    int nb = bn * BN;
    float4 x0 = *(const float4*)&bi[nb + tx * 4];
    float4 y0 = *(const float4*)&bh[nb + tx * 4];
    float4 x1 = *(const float4*)&bi[nb + tx * 4 + 64];
    float4 y1 = *(const float4*)&bh[nb + tx * 4 + 64];
    float4 bias0 = make_float4(x0.x + y0.x, x0.y + y0.y, x0.z + y0.z, x0.w + y0.w);
    float4 bias1 = make_float4(x1.x + y1.x, x1.y + y1.y, x1.z + y1.z, x1.w + y1.w);
#pragma unroll
    for (int r = 0; r < 8; ++r) {
        int row_local = (r < 4) ? (ty * 4 + r) : (64 + ty * 4 + (r - 4));
        size_t row = (size_t)(bm * BM + row_local);
        float2 p0 = unpack2(acc[r][0]), p1 = unpack2(acc[r][1]);
        float2 p2 = unpack2(acc[r][2]), p3 = unpack2(acc[r][3]);
        float4 o0 = make_float4(p0.x + bias0.x, p0.y + bias0.y, p1.x + bias0.z, p1.y + bias0.w);
        float4 o1 = make_float4(p2.x + bias1.x, p2.y + bias1.y, p3.x + bias1.z, p3.y + bias1.w);
        *(float4*)&C[row * HID + nb + tx * 4] = o0;
        *(float4*)&C[row * HID + nb + tx * 4 + 64] = o1;
    }
}

// ---------------- recurrence ----------------
// 16 clusters x 8 CTAs; cluster owns 4 batches. CTA r owns features
// [64r, 64r+64). Thread (jq=tid>>3 in 0..31, ks=tid&7): W_hh rows jbase+jq and
// jbase+jq+32, k-slice [64ks, 64ks+64), in 128 registers.
// h lives TRANSPOSED in smem: h[k][b0..b3] (float4 per k), segment ks padded to
// 516 floats so the 8 ks-lanes of a warp LDS.128 are bank-disjoint (1 phase).
// One LDS.128 (4 batches at one k) feeds 8 fma2 (2 features x 2 batch-pairs).
// Reduce over the 8 ks-lanes via shfl.bfly; lane ks -> (feature fs=ks>>2,
// batch wb=ks&3) applies tanh, stages, and the CTA pushes its 64-float4 slice
// to all 8 CTAs via st.shared::cluster.v4 + one remote release-arrive per dest
// on each CTA's mbarrier (count=8). Consumers acquire-wait on parity.
// Last step pushes nothing; trailing cluster barrier prevents exit-in-flight.
#define SEG 516
#define HBUFV (8 * SEG)              // 4128 floats per buffer
#define HBUF_BYTES (HBUFV * 4)

__global__ void __cluster_dims__(8, 1, 1) __launch_bounds__(256, 1)
rnn_layer_kernel(const float* __restrict__ xterm,  // E' (layer0) or xb1 (layer1)
                 const int* __restrict__ src,      // tokens (layer0) or nullptr
                 const float* __restrict__ Whh,    // [512][512]
                 float* __restrict__ ys,           // [S][B][512] or nullptr
                 float* __restrict__ outh)         // [64][512] final hidden
{
    __shared__ __align__(16) float sH[2 * HBUFV];     // ~33KB
    __shared__ __align__(16) float4 sStage[64];
    __shared__ __align__(8) unsigned long long sBarSto;

    const unsigned rank = ctarank();
    const int cid = blockIdx.x >> 3;
    const int gb0 = cid << 2;
    const int jbase = (int)rank << 6;
    const int tid = threadIdx.x;
    const int jq = tid >> 3;       // 0..31
    const int ks = tid & 7;        // 0..7 k-segment
    const int f0 = jbase + jq;
    const int f1 = f0 + 32;

    // W slices in registers (full unroll keeps arrays in regs)
    float w0[64], w1[64];
#pragma unroll
    for (int i = 0; i < 64; ++i) {
        w0[i] = Whh[(size_t)f0 * HID + ks * 64 + i];
        w1[i] = Whh[(size_t)f1 * HID + ks * 64 + i];
    }

    for (int i = tid; i < 2 * HBUFV; i += 256) sH[i] = 0.0f;
    if (tid == 0)
        asm volatile("mbarrier.init.shared.b64 [%0], %1;"
                     :: "r"(smem_u32(&sBarSto)), "r"(8u) : "memory");
    __syncthreads();
    asm volatile("barrier.cluster.arrive.aligned;" ::: "memory");
    asm volatile("barrier.cluster.wait.aligned;" ::: "memory");

    // push mapping: warp w -> dest rank w; lane q -> float4 slots q, q+32
    const int pr = tid >> 5, q0 = tid & 31;
    unsigned pushA;
    {
        unsigned l = smem_u32(&sH[(int)rank * SEG + q0 * 4]);
        asm("mapa.shared::cluster.u32 %0, %1, %2;" : "=r"(pushA) : "r"(l), "r"(pr));
    }
    const unsigned pushB = pushA + 32 * 16;
    const unsigned barL = smem_u32(&sBarSto);
    unsigned barR = 0;
    if (tid < 8)
        asm("mapa.shared::cluster.u32 %0, %1, %2;" : "=r"(barR) : "r"(barL), "r"(tid));

    // writer identity: lane ks -> (feature select fs, batch wb)
    const int fs = ks >> 2, wb = ks & 3;
    const int wf = jbase + jq + (fs << 5);   // this thread's output feature
    const int brow = gb0 + wb;               // this thread's output batch
    const int wsl = (jq + (fs << 5)) * 4 + wb;  // stage slot (float index)

    // x-term prefetch pipeline
    float xv;
    int tok_n = 0;
    if (src) {
        int t0 = src[(size_t)brow * SEQ + 0];
        xv = __ldg(&xterm[(size_t)t0 * HID + wf]);
        tok_n = src[(size_t)brow * SEQ + 1];
    } else {
        xv = __ldg(&xterm[(size_t)brow * HID + wf]);
    }

    unsigned phase = 0;

    for (int t = 0; t < SEQ; ++t) {
        if (t > 0) { mbar_wait(barL, phase); phase ^= 1u; }

        const float* hb = sH + (t & 1) * HBUFV + ks * SEG;
        unsigned long long a01_0 = 0, a23_0 = 0, a01_1 = 0, a23_1 = 0;
#pragma unroll
        for (int i = 0; i < 64; ++i) {
            ulonglong2 hq = *(const ulonglong2*)(hb + i * 4);  // (b0,b1),(b2,b3)
            unsigned long long p0 = pack2(w0[i]);
            unsigned long long p1 = pack2(w1[i]);
            fma2(a01_0, p0, hq.x); fma2(a23_0, p0, hq.y);
            fma2(a01_1, p1, hq.x); fma2(a23_1, p1, hq.y);
        }
        // reduce over the 8 ks-lanes
#pragma unroll
        for (int m = 1; m <= 4; m <<= 1) {
            a01_0 = add2(a01_0, __shfl_xor_sync(0xffffffffu, a01_0, m));
            a23_0 = add2(a23_0, __shfl_xor_sync(0xffffffffu, a23_0, m));
            a01_1 = add2(a01_1, __shfl_xor_sync(0xffffffffu, a01_1, m));
            a23_1 = add2(a23_1, __shfl_xor_sync(0xffffffffu, a23_1, m));
        }
        unsigned long long ap = fs ? ((wb < 2) ? a01_1 : a23_1)
                                   : ((wb < 2) ? a01_0 : a23_0);
        float dot = (wb & 1) ? hi2(ap) : lo2(ap);
        float h = tanhf(dot + xv);
        ((float*)sStage)[wsl] = h;

        // overlap: prefetch next x, drain global stores
        if (src) {
            xv = __ldg(&xterm[(size_t)tok_n * HID + wf]);
            int tnx = (t + 2 < SEQ) ? (t + 2) : (SEQ - 1);
            tok_n = src[(size_t)brow * SEQ + tnx];
        } else {
            int tnx = (t + 1 < SEQ) ? (t + 1) : (SEQ - 1);
            xv = __ldg(&xterm[((size_t)tnx * BATCH + brow) * HID + wf]);
        }
        if (ys) ys[((size_t)t * BATCH + brow) * HID + wf] = h;
        if (t == SEQ - 1) outh[(size_t)brow * HID + wf] = h;

        __syncthreads();   // stage complete

        if (t < SEQ - 1) {
            const unsigned bo = ((t + 1) & 1) ? (unsigned)HBUF_BYTES : 0u;
            float4 v0 = sStage[q0];
            float4 v1 = sStage[q0 + 32];
            asm volatile("st.shared::cluster.v4.f32 [%0], {%1, %2, %3, %4};"
                         :: "r"(pushA + bo), "f"(v0.x), "f"(v0.y), "f"(v0.z), "f"(v0.w) : "memory");
            asm volatile("st.shared::cluster.v4.f32 [%0], {%1, %2, %3, %4};"
                         :: "r"(pushB + bo), "f"(v1.x), "f"(v1.y), "f"(v1.z), "f"(v1.w) : "memory");
            __syncthreads();   // all pushes issued
            if (tid < 8)
                asm volatile("mbarrier.arrive.release.cluster.shared::cluster.b64 _, [%0];"
                             :: "r"(barR) : "memory");
        }
    }

    // no CTA may exit while peers' DSMEM ops may be in flight
    asm volatile("barrier.cluster.arrive.aligned;" ::: "memory");
    asm volatile("barrier.cluster.wait.aligned;" ::: "memory");
}

// ---------------- launch ----------------
extern "C" void kernel_launch(void* const* d_in, const int* in_sizes, int n_in,
                              void* d_out, int out_size)
{
    const int* src = (const int*)d_in[0];
    const float* embed = (const float*)d_in[1];
    const float* W_ih = (const float*)d_in[2];   // [2][512][512]
    const float* W_hh = (const float*)d_in[3];   // [2][512][512]
    const float* b_ih = (const float*)d_in[4];   // [2][512]
    const float* b_hh = (const float*)d_in[5];   // [2][512]
    float* out = (float*)d_out;                  // [2][64][512]

    float *pE, *pYs, *pXb;
    cudaGetSymbolAddress((void**)&pE, g_E);
    cudaGetSymbolAddress((void**)&pYs, g_ys);
    cudaGetSymbolAddress((void**)&pXb, g_xb);

    // 1) E' = embed @ W_ih0^T + b_ih0 + b_hh0
    gemm_bias_kernel<<<dim3(VOCAB / BM, HID / BN), 256>>>(embed, W_ih, b_ih, b_hh, pE);
    // 2) layer-0 recurrence (gathers E'[src]), writes ys + final h
    rnn_layer_kernel<<<128, 256>>>(pE, src, W_hh, pYs, out);
    // 3) xb1 = ys @ W_ih1^T + b_ih1 + b_hh1
    gemm_bias_kernel<<<dim3(SEQ * BATCH / BM, HID / BN), 256>>>(
        pYs, W_ih + (size_t)HID * HID, b_ih + HID, b_hh + HID, pXb);
    // 4) layer-1 recurrence, writes final h
    rnn_layer_kernel<<<128, 256>>>(
        pXb, nullptr, W_hh + (size_t)HID * HID, nullptr, out + (size_t)BATCH * HID);
}

// round 14
// speedup vs baseline: 1.9942x; 1.5984x over previous
#include <cuda_runtime.h>
#include <cstdint>
#include <cstddef>

#define HID 512
#define SEQ 2048
#define BATCH 64
#define VOCAB 32000

#define CHUNK 128
#define NCHUNK (SEQ / CHUNK)

// ---------------- scratch ----------------
__device__ float g_E[(size_t)VOCAB * HID];          // E' = embed @ W_ih0^T + biases
__device__ float g_ys[(size_t)SEQ * BATCH * HID];   // layer-0 outputs
__device__ float g_xb[(size_t)SEQ * BATCH * HID];   // layer-1 input term
__device__ float g_h1[(size_t)BATCH * HID];         // layer-1 h state across chunks

// ---------------- helpers ----------------
__device__ __forceinline__ unsigned smem_u32(const void* p) {
    unsigned r;
    asm("{ .reg .u64 t; cvta.to.shared.u64 t, %1; cvt.u32.u64 %0, t; }" : "=r"(r) : "l"(p));
    return r;
}
__device__ __forceinline__ unsigned ctarank() {
    unsigned r; asm("mov.u32 %0, %%cluster_ctarank;" : "=r"(r)); return r;
}
__device__ __forceinline__ void fma2(unsigned long long& d, unsigned long long a, unsigned long long b) {
    asm("fma.rn.f32x2 %0, %1, %2, %0;" : "+l"(d) : "l"(a), "l"(b));
}
__device__ __forceinline__ unsigned long long add2(unsigned long long a, unsigned long long b) {
    unsigned long long r;
    asm("add.rn.f32x2 %0, %1, %2;" : "=l"(r) : "l"(a), "l"(b));
    return r;
}
__device__ __forceinline__ unsigned long long pack2(float a) {
    unsigned long long r; asm("mov.b64 %0, {%1, %1};" : "=l"(r) : "f"(a)); return r;
}
__device__ __forceinline__ float lo2(unsigned long long a) { return __uint_as_float((unsigned)a); }
__device__ __forceinline__ float hi2(unsigned long long a) { return __uint_as_float((unsigned)(a >> 32)); }
__device__ __forceinline__ float2 unpack2(unsigned long long a) {
    return make_float2(lo2(a), hi2(a));
}
__device__ __forceinline__ void mbar_wait(unsigned mbar, unsigned parity) {
    unsigned done;
    asm volatile(
        "{\n\t.reg .pred p;\n\t"
        "mbarrier.try_wait.parity.acquire.cluster.shared::cta.b64 p, [%1], %2;\n\t"
        "selp.b32 %0, 1, 0, p;\n\t}"
        : "=r"(done) : "r"(mbar), "r"(parity) : "memory");
    if (!done) {
        asm volatile(
            "{\n\t.reg .pred P1;\n\t"
            "WL_%=:\n\t"
            "mbarrier.try_wait.parity.acquire.cluster.shared::cta.b64 P1, [%0], %1, 0x989680;\n\t"
            "@P1 bra.uni WD_%=;\n\t"
            "bra.uni WL_%=;\n\t"
            "WD_%=:\n\t}"
            :: "r"(mbar), "r"(parity) : "memory");
    }
}

// ---------------- GEMM: C[M][512] = A[M][512] @ W[512][512]^T + bi + bh ------
#define BM 128
#define BN 128
#define BK 16

__global__ void __launch_bounds__(256)
gemm_bias_kernel(const float* __restrict__ A, const float* __restrict__ W,
                 const float* __restrict__ bi, const float* __restrict__ bh,
                 float* __restrict__ C)
{
    __shared__ float As[BK][BM + 4];
    __shared__ float Bs[BK][BN + 4];

    int bm = blockIdx.x, bn = blockIdx.y;
    int tid = threadIdx.x;
    int tx = tid & 15, ty = tid >> 4;
    int ar = tid >> 2;
    int ac = (tid & 3) << 2;

    const float* Ap = A + (size_t)bm * BM * HID;
    const float* Wp = W + (size_t)bn * BN * HID;

    unsigned long long acc[8][4];
#pragma unroll
    for (int r = 0; r < 8; ++r)
#pragma unroll
        for (int c = 0; c < 4; ++c) acc[r][c] = 0ULL;

    for (int k0 = 0; k0 < HID; k0 += BK) {
        float4 a0 = *(const float4*)&Ap[(size_t)ar * HID + k0 + ac];
        float4 a1 = *(const float4*)&Ap[(size_t)(ar + 64) * HID + k0 + ac];
        float4 b0 = *(const float4*)&Wp[(size_t)ar * HID + k0 + ac];
        float4 b1 = *(const float4*)&Wp[(size_t)(ar + 64) * HID + k0 + ac];
        __syncthreads();
        As[ac + 0][ar] = a0.x; As[ac + 1][ar] = a0.y; As[ac + 2][ar] = a0.z; As[ac + 3][ar] = a0.w;
        As[ac + 0][ar + 64] = a1.x; As[ac + 1][ar + 64] = a1.y; As[ac + 2][ar + 64] = a1.z; As[ac + 3][ar + 64] = a1.w;
        Bs[ac + 0][ar] = b0.x; Bs[ac + 1][ar] = b0.y; Bs[ac + 2][ar] = b0.z; Bs[ac + 3][ar] = b0.w;
        Bs[ac + 0][ar + 64] = b1.x; Bs[ac + 1][ar + 64] = b1.y; Bs[ac + 2][ar + 64] = b1.z; Bs[ac + 3][ar + 64] = b1.w;
        __syncthreads();
#pragma unroll
        for (int k = 0; k < BK; ++k) {
            float4 av0 = *(const float4*)&As[k][ty * 4];
            float4 av1 = *(const float4*)&As[k][ty * 4 + 64];
            ulonglong2 bv0 = *(const ulonglong2*)&Bs[k][tx * 4];
            ulonglong2 bv1 = *(const ulonglong2*)&Bs[k][tx * 4 + 64];
            unsigned long long am[8];
            am[0] = pack2(av0.x); am[1] = pack2(av0.y); am[2] = pack2(av0.z); am[3] = pack2(av0.w);
            am[4] = pack2(av1.x); am[5] = pack2(av1.y); am[6] = pack2(av1.z); am[7] = pack2(av1.w);
#pragma unroll
            for (int r = 0; r < 8; ++r) {
                fma2(acc[r][0], am[r], bv0.x);
                fma2(acc[r][1], am[r], bv0.y);
                fma2(acc[r][2], am[r], bv1.x);
                fma2(acc[r][3], am[r], bv1.y);
            }
        }
    }

    int nb = bn * BN;
    float4 x0 = *(const float4*)&bi[nb + tx * 4];
    float4 y0 = *(const float4*)&bh[nb + tx * 4];
    float4 x1 = *(const float4*)&bi[nb + tx * 4 + 64];
    float4 y1 = *(const float4*)&bh[nb + tx * 4 + 64];
    float4 bias0 = make_float4(x0.x + y0.x, x0.y + y0.y, x0.z + y0.z, x0.w + y0.w);
    float4 bias1 = make_float4(x1.x + y1.x, x1.y + y1.y, x1.z + y1.z, x1.w + y1.w);
#pragma unroll
    for (int r = 0; r < 8; ++r) {
        int row_local = (r < 4) ? (ty * 4 + r) : (64 + ty * 4 + (r - 4));
        size_t row = (size_t)(bm * BM + row_local);
        float2 p0 = unpack2(acc[r][0]), p1 = unpack2(acc[r][1]);
        float2 p2 = unpack2(acc[r][2]), p3 = unpack2(acc[r][3]);
        float4 o0 = make_float4(p0.x + bias0.x, p0.y + bias0.y, p1.x + bias0.z, p1.y + bias0.w);
        float4 o1 = make_float4(p2.x + bias1.x, p2.y + bias1.y, p3.x + bias1.z, p3.y + bias1.w);
        *(float4*)&C[row * HID + nb + tx * 4] = o0;
        *(float4*)&C[row * HID + nb + tx * 4 + 64] = o1;
    }
}

// ---------------- recurrence chunk kernel ----------------
// 8 clusters x 8 CTAs (64 CTAs). Cluster owns 8 batches; CTA r owns features
// [64r, 64r+64) with W rows in 128 registers (2 feats x 64-k slice / thread).
// h transposed in smem: [buf][kseg 8][k 64][batch 8], seg stride 516 floats
// (4-bank offset per kseg -> warp LDS.128 conflict-free). Per k: 2 LDS.128
// feed 8 fma2. 8-lane butterfly reduce (packed), lane ks -> (feature fs=ks&1,
// batch pair bp=ks>>1) applies tanh to 2 batches, stages float2; the CTA's
// 2KB slice is pushed to all 8 CTAs (st.shared::cluster.v4, 4/thread) +
// remote release-arrives on per-CTA mbarriers (count=8). Chunked over t:
// [t0, t0+CHUNK), h state carried via hIn/ys (L0) or g_h1 (L1).
#define SEG 516
#define HBUFV (8 * SEG)
#define HBUF_BYTES (HBUFV * 4)

__global__ void __cluster_dims__(8, 1, 1) __launch_bounds__(256, 1)
rnn_chunk_kernel(const float* __restrict__ xterm,  // E' (L0) or g_xb (L1)
                 const int* __restrict__ src,      // tokens (L0) or nullptr
                 const float* __restrict__ Whh,    // [512][512]
                 float* __restrict__ ys,           // [S][B][512] (L0) or nullptr
                 float* __restrict__ outh,         // final hidden [64][512] or nullptr
                 const float* __restrict__ hIn,    // [b][512] h(t0-1) or nullptr
                 float* __restrict__ hOut,         // [b][512] h(t0+CHUNK-1) or nullptr
                 int t0)
{
    __shared__ __align__(16) float sH[2 * HBUFV];
    __shared__ __align__(16) float4 sStage[128];   // 512 floats: [feat 64][batch 8]
    __shared__ __align__(8) unsigned long long sBarSto;

    const unsigned rank = ctarank();
    const int cid = blockIdx.x >> 3;
    const int gb0 = cid << 3;                 // 8 batches per cluster
    const int jbase = (int)rank << 6;
    const int tid = threadIdx.x;
    const int jq = tid >> 3;                  // 0..31
    const int ks = tid & 7;                   // k segment
    const int f0 = jbase + jq;
    const int f1 = f0 + 32;

    float w0[64], w1[64];
#pragma unroll
    for (int i = 0; i < 64; ++i) {
        w0[i] = Whh[(size_t)f0 * HID + ks * 64 + i];
        w1[i] = Whh[(size_t)f1 * HID + ks * 64 + i];
    }

    // init h buffer for parity t0&1
    if (hIn) {
        for (int idx = tid; idx < 4096; idx += 256) {
            int bl = idx & 7, k = idx >> 3;
            sH[(t0 & 1) * HBUFV + (k >> 6) * SEG + (k & 63) * 8 + bl] =
                hIn[(size_t)(gb0 + bl) * HID + k];
        }
    } else {
        for (int i = tid; i < 2 * HBUFV; i += 256) sH[i] = 0.0f;
    }
    if (tid == 0)
        asm volatile("mbarrier.init.shared.b64 [%0], %1;"
                     :: "r"(smem_u32(&sBarSto)), "r"(8u) : "memory");
    __syncthreads();
    asm volatile("barrier.cluster.arrive.aligned;" ::: "memory");
    asm volatile("barrier.cluster.wait.aligned;" ::: "memory");

    // push mapping: warp pr -> dest rank pr; each lane pushes 4x float4
    const int pr = tid >> 5, q0 = tid & 31;
    unsigned pushBase;
    {
        unsigned l = smem_u32(&sH[(int)rank * SEG]);
        asm("mapa.shared::cluster.u32 %0, %1, %2;" : "=r"(pushBase) : "r"(l), "r"(pr));
    }
    const unsigned barL = smem_u32(&sBarSto);
    unsigned barR = 0;
    if (tid < 8)
        asm("mapa.shared::cluster.u32 %0, %1, %2;" : "=r"(barR) : "r"(barL), "r"(tid));

    // writer identity: lane ks -> (feature fs = ks&1, batch pair bp = ks>>1)
    const int fs = ks & 1, bp = ks >> 1;
    const int wf = jbase + jq + (fs << 5);
    const int bA = gb0 + 2 * bp, bB = bA + 1;
    const int wslot = (jq + (fs << 5)) * 4 + bp;  // float2 slot in stage

    // x prefetch for step t0
    float xvA, xvB;
    if (src) {
        int tA = src[(size_t)bA * SEQ + t0];
        int tB = src[(size_t)bB * SEQ + t0];
        xvA = __ldg(&xterm[(size_t)tA * HID + wf]);
        xvB = __ldg(&xterm[(size_t)tB * HID + wf]);
    } else {
        xvA = __ldg(&xterm[((size_t)t0 * BATCH + bA) * HID + wf]);
        xvB = __ldg(&xterm[((size_t)t0 * BATCH + bB) * HID + wf]);
    }

    unsigned phase = 0;
    const int tEnd = t0 + CHUNK;

    for (int t = t0; t < tEnd; ++t) {
        if (t > t0) { mbar_wait(barL, phase); phase ^= 1u; }

        const float* hb = sH + (t & 1) * HBUFV + ks * SEG;
        unsigned long long a01_0 = 0, a23_0 = 0, a45_0 = 0, a67_0 = 0;
        unsigned long long a01_1 = 0, a23_1 = 0, a45_1 = 0, a67_1 = 0;
#pragma unroll
        for (int i = 0; i < 64; ++i) {
            ulonglong2 hA = *(const ulonglong2*)(hb + i * 8);        // b0..b3
            ulonglong2 hB = *(const ulonglong2*)(hb + i * 8 + 4);    // b4..b7
            unsigned long long p0 = pack2(w0[i]);
            unsigned long long p1 = pack2(w1[i]);
            fma2(a01_0, p0, hA.x); fma2(a23_0, p0, hA.y);
            fma2(a45_0, p0, hB.x); fma2(a67_0, p0, hB.y);
            fma2(a01_1, p1, hA.x); fma2(a23_1, p1, hA.y);
            fma2(a45_1, p1, hB.x); fma2(a67_1, p1, hB.y);
        }
#pragma unroll
        for (int m = 1; m <= 4; m <<= 1) {
            a01_0 = add2(a01_0, __shfl_xor_sync(0xffffffffu, a01_0, m));
            a23_0 = add2(a23_0, __shfl_xor_sync(0xffffffffu, a23_0, m));
            a45_0 = add2(a45_0, __shfl_xor_sync(0xffffffffu, a45_0, m));
            a67_0 = add2(a67_0, __shfl_xor_sync(0xffffffffu, a67_0, m));
            a01_1 = add2(a01_1, __shfl_xor_sync(0xffffffffu, a01_1, m));
            a23_1 = add2(a23_1, __shfl_xor_sync(0xffffffffu, a23_1, m));
            a45_1 = add2(a45_1, __shfl_xor_sync(0xffffffffu, a45_1, m));
            a67_1 = add2(a67_1, __shfl_xor_sync(0xffffffffu, a67_1, m));
        }
        unsigned long long s01 = fs ? a01_1 : a01_0;
        unsigned long long s23 = fs ? a23_1 : a23_0;
        unsigned long long s45 = fs ? a45_1 : a45_0;
        unsigned long long s67 = fs ? a67_1 : a67_0;
        unsigned long long ap = (bp == 0) ? s01 : (bp == 1) ? s23 : (bp == 2) ? s45 : s67;

        float hA = tanhf(lo2(ap) + xvA);
        float hB = tanhf(hi2(ap) + xvB);
        ((float2*)sStage)[wslot] = make_float2(hA, hB);
        __syncthreads();

        const bool last = (t == tEnd - 1);
        if (!last) {
            const unsigned bo = (unsigned)(((t + 1) & 1)) * HBUF_BYTES;
#pragma unroll
            for (int i = 0; i < 4; ++i) {
                int q = q0 + 32 * i;
                float4 v = sStage[q];
                asm volatile("st.shared::cluster.v4.f32 [%0], {%1, %2, %3, %4};"
                             :: "r"(pushBase + bo + (unsigned)q * 16u),
                                "f"(v.x), "f"(v.y), "f"(v.z), "f"(v.w) : "memory");
            }
            __syncthreads();
            if (tid < 8)
                asm volatile("mbarrier.arrive.release.cluster.shared::cluster.b64 _, [%0];"
                             :: "r"(barR) : "memory");
        }

        // off critical path: global stores + next-x prefetch
        if (ys) {
            ys[((size_t)t * BATCH + bA) * HID + wf] = hA;
            ys[((size_t)t * BATCH + bB) * HID + wf] = hB;
        }
        if (last && hOut) {
            hOut[(size_t)bA * HID + wf] = hA;
            hOut[(size_t)bB * HID + wf] = hB;
        }
        if (t == SEQ - 1 && outh) {
            outh[(size_t)bA * HID + wf] = hA;
            outh[(size_t)bB * HID + wf] = hB;
        }
        {
            int tn = (t + 1 < tEnd) ? (t + 1) : (tEnd - 1);
            if (src) {
                int tA = src[(size_t)bA * SEQ + tn];
                int tB = src[(size_t)bB * SEQ + tn];
                xvA = __ldg(&xterm[(size_t)tA * HID + wf]);
                xvB = __ldg(&xterm[(size_t)tB * HID + wf]);
            } else {
                xvA = __ldg(&xterm[((size_t)tn * BATCH + bA) * HID + wf]);
                xvB = __ldg(&xterm[((size_t)tn * BATCH + bB) * HID + wf]);
            }
        }
    }

    asm volatile("barrier.cluster.arrive.aligned;" ::: "memory");
    asm volatile("barrier.cluster.wait.aligned;" ::: "memory");
}

// ---------------- launch ----------------
extern "C" void kernel_launch(void* const* d_in, const int* in_sizes, int n_in,
                              void* d_out, int out_size)
{
    const int* src = (const int*)d_in[0];
    const float* embed = (const float*)d_in[1];
    const float* W_ih = (const float*)d_in[2];   // [2][512][512]
    const float* W_hh = (const float*)d_in[3];   // [2][512][512]
    const float* b_ih = (const float*)d_in[4];   // [2][512]
    const float* b_hh = (const float*)d_in[5];   // [2][512]
    float* out = (float*)d_out;                  // [2][64][512]

    float *pE, *pYs, *pXb, *pH1;
    cudaGetSymbolAddress((void**)&pE, g_E);
    cudaGetSymbolAddress((void**)&pYs, g_ys);
    cudaGetSymbolAddress((void**)&pXb, g_xb);
    cudaGetSymbolAddress((void**)&pH1, g_h1);

    static bool s_init = false;
    static cudaStream_t sB;
    static cudaEvent_t evPipe[NCHUNK], evJoin;
    if (!s_init) {
        cudaStreamCreateWithFlags(&sB, cudaStreamNonBlocking);
        for (int i = 0; i < NCHUNK; ++i)
            cudaEventCreateWithFlags(&evPipe[i], cudaEventDisableTiming);
        cudaEventCreateWithFlags(&evJoin, cudaEventDisableTiming);
        s_init = true;
    }

    // stream 0 (captured): E' = embed @ W_ih0^T + b0, then L0 chunks
    gemm_bias_kernel<<<dim3(VOCAB / BM, HID / BN), 256>>>(embed, W_ih, b_ih, b_hh, pE);

    const float* Wih1 = W_ih + (size_t)HID * HID;
    const float* Whh0 = W_hh;
    const float* Whh1 = W_hh + (size_t)HID * HID;

    for (int c = 0; c < NCHUNK; ++c) {
        int t0 = c * CHUNK;
        // layer-0 chunk (stream 0): h state carried via ys
        rnn_chunk_kernel<<<64, 256>>>(
            pE, src, Whh0, pYs, out,
            (c == 0) ? nullptr : pYs + ((size_t)t0 - 1) * BATCH * HID,
            nullptr, t0);
        cudaEventRecord(evPipe[c], 0);

        // stream B: xb chunk gemm + layer-1 chunk
        cudaStreamWaitEvent(sB, evPipe[c], 0);
        gemm_bias_kernel<<<dim3(CHUNK * BATCH / BM, HID / BN), 256, 0, sB>>>(
            pYs + (size_t)t0 * BATCH * HID, Wih1, b_ih + HID, b_hh + HID,
            pXb + (size_t)t0 * BATCH * HID);
        rnn_chunk_kernel<<<64, 256, 0, sB>>>(
            pXb, nullptr, Whh1, nullptr, out + (size_t)BATCH * HID,
            (c == 0) ? nullptr : pH1, pH1, t0);
    }
    cudaEventRecord(evJoin, sB);
    cudaStreamWaitEvent(0, evJoin, 0);
}